// round 4
// baseline (speedup 1.0000x reference)
#include <cuda_runtime.h>
#include <math_constants.h>

#define B1 4096
#define B2 100000
#define DDIM 64
#define K 16
#define QB 256
#define NQB (B1 / QB)          // 16 query blocks
#define NCH 9                  // y chunks -> 16*9 = 144 CTAs, one wave
#define CHUNK 11112            // ceil(100000/9)
#define TN 32                  // y tile points per shared-mem stage

// Scratch (allocation-free rule: __device__ globals)
__device__ float g_y2[B2];
__device__ float g_cand_d[NQB * NCH * QB * K];
__device__ int   g_cand_i[NQB * NCH * QB * K];

// ---------------------------------------------------------------------------
// Kernel 1: y2[i] = fp32( fp64 sum of y[i][d]^2 )  — correctly-rounded norm.
// ---------------------------------------------------------------------------
__global__ void y2_kernel(const float* __restrict__ y) {
    int i = blockIdx.x * blockDim.x + threadIdx.x;
    if (i < B2) {
        const float4* r = reinterpret_cast<const float4*>(y + (size_t)i * DDIM);
        double s = 0.0;
        #pragma unroll
        for (int t = 0; t < 16; ++t) {
            float4 v = r[t];
            s += (double)v.x * (double)v.x;
            s += (double)v.y * (double)v.y;
            s += (double)v.z * (double)v.z;
            s += (double)v.w * (double)v.w;
        }
        g_y2[i] = (float)s;
    }
}

// ---------------------------------------------------------------------------
// Kernel 2: per (query-block, y-chunk) CTA. Thread owns one query.
// dot computed as STRICT sequential fp32 fmaf chain over k=0..63 (matches
// Eigen gebp / cuBLAS SIMT single-accumulator k-order). Two candidates in
// flight per thread for FFMA-pipe saturation.
// ---------------------------------------------------------------------------
__global__ void __launch_bounds__(QB, 1) knn_partial(
    const float* __restrict__ x, const float* __restrict__ y) {
    __shared__ __align__(16) float ys[TN * DDIM];
    __shared__ float ys2[TN];

    const int qb  = blockIdx.x;
    const int c   = blockIdx.y;
    const int tid = threadIdx.x;
    const int q   = qb * QB + tid;

    // Query row in 64 scalar registers.
    float xr[DDIM];
    {
        const float4* xrow = reinterpret_cast<const float4*>(x + (size_t)q * DDIM);
        #pragma unroll
        for (int t = 0; t < 16; ++t) {
            float4 v = xrow[t];
            xr[4 * t + 0] = v.x; xr[4 * t + 1] = v.y;
            xr[4 * t + 2] = v.z; xr[4 * t + 3] = v.w;
        }
    }
    // x2 in fp64 (per-query constant; uniform shift, rank-irrelevant anyway).
    float x2;
    {
        double s = 0.0;
        #pragma unroll
        for (int k = 0; k < DDIM; ++k) s += (double)xr[k] * (double)xr[k];
        x2 = (float)s;
    }

    float bd[K];           // sorted ascending DISTANCES (sqrt domain)
    int   bi[K];
    #pragma unroll
    for (int u = 0; u < K; ++u) { bd[u] = CUDART_INF_F; bi[u] = 2147483647; }
    float gate2 = CUDART_INF_F;   // safe d^2 bound for "might beat bd[15]"

    const int j0 = c * CHUNK;
    const int j1 = min(j0 + CHUNK, B2);

    for (int t0 = j0; t0 < j1; t0 += TN) {
        __syncthreads();
        // Stage 32 y rows (8 KB) — 512 float4 segments over 256 threads.
        #pragma unroll
        for (int it = 0; it < 2; ++it) {
            int idx = tid + it * QB;
            int r = idx >> 4;
            int s = idx & 15;
            int row = t0 + r;
            float4 v = make_float4(0.f, 0.f, 0.f, 0.f);
            if (row < j1)
                v = reinterpret_cast<const float4*>(y + (size_t)row * DDIM)[s];
            reinterpret_cast<float4*>(ys)[r * 16 + s] = v;
        }
        if (tid < TN) {
            int row = t0 + tid;
            ys2[tid] = (row < j1) ? g_y2[row] : CUDART_INF_F;
        }
        __syncthreads();

        #pragma unroll 1
        for (int jj = 0; jj < TN; jj += 2) {
            const float* y0 = ys + jj * DDIM;
            const float* y1 = y0 + DDIM;
            // Strict sequential fp32 FMA chains (order is load-bearing).
            float a0 = 0.f, a1 = 0.f;
            #pragma unroll
            for (int k = 0; k < DDIM; ++k) {
                a0 = fmaf(xr[k], y0[k], a0);
                a1 = fmaf(xr[k], y1[k], a1);
            }
            float d2_0 = __fsub_rn(__fadd_rn(x2, ys2[jj]),
                                   __fmul_rn(2.f, a0));
            float d2_1 = __fsub_rn(__fadd_rn(x2, ys2[jj + 1]),
                                   __fmul_rn(2.f, a1));

            // Candidate jj (lower index first — stability).
            if (d2_0 < gate2) {
                float dv = __fsqrt_rn(fmaxf(d2_0, 0.f));
                if (dv < bd[K - 1]) {
                    int id = t0 + jj;
                    #pragma unroll
                    for (int u = K - 1; u >= 1; --u) {
                        bool gtc = bd[u]     > dv;
                        bool gtp = bd[u - 1] > dv;
                        float nd = gtp ? bd[u - 1] : dv;
                        int   ni = gtp ? bi[u - 1] : id;
                        if (gtc) { bd[u] = nd; bi[u] = ni; }
                    }
                    if (bd[0] > dv) { bd[0] = dv; bi[0] = id; }
                    float b = bd[K - 1];
                    gate2 = (b == CUDART_INF_F) ? CUDART_INF_F
                                                : b * b * 1.000002f;
                }
            }
            // Candidate jj+1.
            if (d2_1 < gate2) {
                float dv = __fsqrt_rn(fmaxf(d2_1, 0.f));
                if (dv < bd[K - 1]) {
                    int id = t0 + jj + 1;
                    #pragma unroll
                    for (int u = K - 1; u >= 1; --u) {
                        bool gtc = bd[u]     > dv;
                        bool gtp = bd[u - 1] > dv;
                        float nd = gtp ? bd[u - 1] : dv;
                        int   ni = gtp ? bi[u - 1] : id;
                        if (gtc) { bd[u] = nd; bi[u] = ni; }
                    }
                    if (bd[0] > dv) { bd[0] = dv; bi[0] = id; }
                    float b = bd[K - 1];
                    gate2 = (b == CUDART_INF_F) ? CUDART_INF_F
                                                : b * b * 1.000002f;
                }
            }
        }
    }

    const long long base = ((long long)(qb * NCH + c) * QB + tid) * K;
    #pragma unroll
    for (int u = 0; u < K; ++u) {
        g_cand_d[base + u] = bd[u];   // distances (sqrt domain)
        g_cand_i[base + u] = bi[u];
    }
}

// ---------------------------------------------------------------------------
// Kernel 3: merge NCH*16 candidates per query; chunks ascending + strict '<'
// insert => stable index-order ties, matching lax.top_k.
// ---------------------------------------------------------------------------
__global__ void knn_merge(float* __restrict__ out) {
    const int tid = threadIdx.x;
    const int qb  = blockIdx.x;
    const int q   = qb * QB + tid;

    float bd[K];
    int   bi[K];
    #pragma unroll
    for (int u = 0; u < K; ++u) { bd[u] = CUDART_INF_F; bi[u] = 2147483647; }

    for (int cc = 0; cc < NCH; ++cc) {
        const long long base = ((long long)(qb * NCH + cc) * QB + tid) * K;
        #pragma unroll
        for (int u2 = 0; u2 < K; ++u2) {
            float dv = g_cand_d[base + u2];
            int   id = g_cand_i[base + u2];
            if (dv < bd[K - 1]) {
                #pragma unroll
                for (int u = K - 1; u >= 1; --u) {
                    bool gtc = bd[u]     > dv;
                    bool gtp = bd[u - 1] > dv;
                    float nd = gtp ? bd[u - 1] : dv;
                    int   ni = gtp ? bi[u - 1] : id;
                    if (gtc) { bd[u] = nd; bi[u] = ni; }
                }
                if (bd[0] > dv) { bd[0] = dv; bi[0] = id; }
            } else {
                break;  // candidate lists are sorted ascending
            }
        }
    }

    #pragma unroll
    for (int u = 0; u < K; ++u) {
        out[(size_t)q * K + u]                  = bd[u];
        out[(size_t)B1 * K + (size_t)q * K + u] = (float)bi[u];
    }
}

// ---------------------------------------------------------------------------
extern "C" void kernel_launch(void* const* d_in, const int* in_sizes, int n_in,
                              void* d_out, int out_size) {
    const float* x = (const float*)d_in[0];
    const float* y = (const float*)d_in[1];
    float* out = (float*)d_out;

    y2_kernel<<<(B2 + 255) / 256, 256>>>(y);
    dim3 grid(NQB, NCH);
    knn_partial<<<grid, QB>>>(x, y);
    knn_merge<<<NQB, QB>>>(out);
}

// round 5
// speedup vs baseline: 1.0014x; 1.0014x over previous
#include <cuda_runtime.h>
#include <math_constants.h>

#define B1 4096
#define B2 100000
#define DDIM 64
#define K 16
#define QB 256
#define NQB (B1 / QB)          // 16 query blocks
#define NCH 9                  // y chunks -> 16*9 = 144 CTAs, one wave
#define CHUNK 11112            // ceil(100000/9)
#define TN 32                  // y tile points per shared-mem stage

// Scratch (allocation-free rule: __device__ globals)
__device__ float g_y2[B2];
__device__ float g_cand_d[NQB * NCH * QB * K];
__device__ int   g_cand_i[NQB * NCH * QB * K];

// ---------------------------------------------------------------------------
// Kernel 1: y2[i] = fp32( fp64 sum of y[i][d]^2 )  — correctly-rounded norm.
// ---------------------------------------------------------------------------
__global__ void y2_kernel(const float* __restrict__ y) {
    int i = blockIdx.x * blockDim.x + threadIdx.x;
    if (i < B2) {
        const float4* r = reinterpret_cast<const float4*>(y + (size_t)i * DDIM);
        double s = 0.0;
        #pragma unroll
        for (int t = 0; t < 16; ++t) {
            float4 v = r[t];
            s += (double)v.x * (double)v.x;
            s += (double)v.y * (double)v.y;
            s += (double)v.z * (double)v.z;
            s += (double)v.w * (double)v.w;
        }
        g_y2[i] = (float)s;
    }
}

// ---------------------------------------------------------------------------
// Kernel 2: per (query-block, y-chunk) CTA. Thread owns one query.
// dot computed as STRICT sequential fp32 fmaf chain over k=0..63 (matches
// Eigen gebp / cuBLAS SIMT single-accumulator k-order). Two candidates in
// flight per thread for FFMA-pipe saturation.
// ---------------------------------------------------------------------------
__global__ void __launch_bounds__(QB, 1) knn_partial(
    const float* __restrict__ x, const float* __restrict__ y) {
    __shared__ __align__(16) float ys[TN * DDIM];
    __shared__ float ys2[TN];

    const int qb  = blockIdx.x;
    const int c   = blockIdx.y;
    const int tid = threadIdx.x;
    const int q   = qb * QB + tid;

    // Query row in 64 scalar registers.
    float xr[DDIM];
    {
        const float4* xrow = reinterpret_cast<const float4*>(x + (size_t)q * DDIM);
        #pragma unroll
        for (int t = 0; t < 16; ++t) {
            float4 v = xrow[t];
            xr[4 * t + 0] = v.x; xr[4 * t + 1] = v.y;
            xr[4 * t + 2] = v.z; xr[4 * t + 3] = v.w;
        }
    }
    // x2 in fp64 (per-query constant; uniform shift, rank-irrelevant anyway).
    float x2;
    {
        double s = 0.0;
        #pragma unroll
        for (int k = 0; k < DDIM; ++k) s += (double)xr[k] * (double)xr[k];
        x2 = (float)s;
    }

    float bd[K];           // sorted ascending DISTANCES (sqrt domain)
    int   bi[K];
    #pragma unroll
    for (int u = 0; u < K; ++u) { bd[u] = CUDART_INF_F; bi[u] = 2147483647; }
    float gate2 = CUDART_INF_F;   // safe d^2 bound for "might beat bd[15]"

    const int j0 = c * CHUNK;
    const int j1 = min(j0 + CHUNK, B2);

    for (int t0 = j0; t0 < j1; t0 += TN) {
        __syncthreads();
        // Stage 32 y rows (8 KB) — 512 float4 segments over 256 threads.
        #pragma unroll
        for (int it = 0; it < 2; ++it) {
            int idx = tid + it * QB;
            int r = idx >> 4;
            int s = idx & 15;
            int row = t0 + r;
            float4 v = make_float4(0.f, 0.f, 0.f, 0.f);
            if (row < j1)
                v = reinterpret_cast<const float4*>(y + (size_t)row * DDIM)[s];
            reinterpret_cast<float4*>(ys)[r * 16 + s] = v;
        }
        if (tid < TN) {
            int row = t0 + tid;
            ys2[tid] = (row < j1) ? g_y2[row] : CUDART_INF_F;
        }
        __syncthreads();

        #pragma unroll 1
        for (int jj = 0; jj < TN; jj += 2) {
            const float* y0 = ys + jj * DDIM;
            const float* y1 = y0 + DDIM;
            // Strict sequential fp32 FMA chains (order is load-bearing).
            float a0 = 0.f, a1 = 0.f;
            #pragma unroll
            for (int k = 0; k < DDIM; ++k) {
                a0 = fmaf(xr[k], y0[k], a0);
                a1 = fmaf(xr[k], y1[k], a1);
            }
            float d2_0 = __fsub_rn(__fadd_rn(x2, ys2[jj]),
                                   __fmul_rn(2.f, a0));
            float d2_1 = __fsub_rn(__fadd_rn(x2, ys2[jj + 1]),
                                   __fmul_rn(2.f, a1));

            // Candidate jj (lower index first — stability).
            if (d2_0 < gate2) {
                float dv = __fsqrt_rn(fmaxf(d2_0, 0.f));
                if (dv < bd[K - 1]) {
                    int id = t0 + jj;
                    #pragma unroll
                    for (int u = K - 1; u >= 1; --u) {
                        bool gtc = bd[u]     > dv;
                        bool gtp = bd[u - 1] > dv;
                        float nd = gtp ? bd[u - 1] : dv;
                        int   ni = gtp ? bi[u - 1] : id;
                        if (gtc) { bd[u] = nd; bi[u] = ni; }
                    }
                    if (bd[0] > dv) { bd[0] = dv; bi[0] = id; }
                    float b = bd[K - 1];
                    gate2 = (b == CUDART_INF_F) ? CUDART_INF_F
                                                : b * b * 1.000002f;
                }
            }
            // Candidate jj+1.
            if (d2_1 < gate2) {
                float dv = __fsqrt_rn(fmaxf(d2_1, 0.f));
                if (dv < bd[K - 1]) {
                    int id = t0 + jj + 1;
                    #pragma unroll
                    for (int u = K - 1; u >= 1; --u) {
                        bool gtc = bd[u]     > dv;
                        bool gtp = bd[u - 1] > dv;
                        float nd = gtp ? bd[u - 1] : dv;
                        int   ni = gtp ? bi[u - 1] : id;
                        if (gtc) { bd[u] = nd; bi[u] = ni; }
                    }
                    if (bd[0] > dv) { bd[0] = dv; bi[0] = id; }
                    float b = bd[K - 1];
                    gate2 = (b == CUDART_INF_F) ? CUDART_INF_F
                                                : b * b * 1.000002f;
                }
            }
        }
    }

    const long long base = ((long long)(qb * NCH + c) * QB + tid) * K;
    #pragma unroll
    for (int u = 0; u < K; ++u) {
        g_cand_d[base + u] = bd[u];   // distances (sqrt domain)
        g_cand_i[base + u] = bi[u];
    }
}

// ---------------------------------------------------------------------------
// Kernel 3: merge NCH*16 candidates per query; chunks ascending + strict '<'
// insert => stable index-order ties, matching lax.top_k.
// ---------------------------------------------------------------------------
__global__ void knn_merge(float* __restrict__ out) {
    const int tid = threadIdx.x;
    const int qb  = blockIdx.x;
    const int q   = qb * QB + tid;

    float bd[K];
    int   bi[K];
    #pragma unroll
    for (int u = 0; u < K; ++u) { bd[u] = CUDART_INF_F; bi[u] = 2147483647; }

    for (int cc = 0; cc < NCH; ++cc) {
        const long long base = ((long long)(qb * NCH + cc) * QB + tid) * K;
        #pragma unroll
        for (int u2 = 0; u2 < K; ++u2) {
            float dv = g_cand_d[base + u2];
            int   id = g_cand_i[base + u2];
            if (dv < bd[K - 1]) {
                #pragma unroll
                for (int u = K - 1; u >= 1; --u) {
                    bool gtc = bd[u]     > dv;
                    bool gtp = bd[u - 1] > dv;
                    float nd = gtp ? bd[u - 1] : dv;
                    int   ni = gtp ? bi[u - 1] : id;
                    if (gtc) { bd[u] = nd; bi[u] = ni; }
                }
                if (bd[0] > dv) { bd[0] = dv; bi[0] = id; }
            } else {
                break;  // candidate lists are sorted ascending
            }
        }
    }

    #pragma unroll
    for (int u = 0; u < K; ++u) {
        out[(size_t)q * K + u]                  = bd[u];
        out[(size_t)B1 * K + (size_t)q * K + u] = (float)bi[u];
    }
}

// ---------------------------------------------------------------------------
extern "C" void kernel_launch(void* const* d_in, const int* in_sizes, int n_in,
                              void* d_out, int out_size) {
    const float* x = (const float*)d_in[0];
    const float* y = (const float*)d_in[1];
    float* out = (float*)d_out;

    y2_kernel<<<(B2 + 255) / 256, 256>>>(y);
    dim3 grid(NQB, NCH);
    knn_partial<<<grid, QB>>>(x, y);
    knn_merge<<<NQB, QB>>>(out);
}

// round 6
// speedup vs baseline: 1.0039x; 1.0025x over previous
#include <cuda_runtime.h>
#include <math_constants.h>

#define B1 4096
#define B2 100000
#define DDIM 64
#define K 16
#define QB 256
#define NQB (B1 / QB)          // 16 query blocks
#define NCH 9                  // y chunks -> 16*9 = 144 CTAs, one wave
#define CHUNK 11112            // ceil(100000/9)
#define TN 32                  // y tile points per shared-mem stage

// Scratch (allocation-free rule: __device__ globals)
__device__ float g_y2[B2];
__device__ float g_cand_d[NQB * NCH * QB * K];
__device__ int   g_cand_i[NQB * NCH * QB * K];

// ---------------------------------------------------------------------------
// Kernel 1: y2[i] = fp32( fp64 sum of y[i][d]^2 )  — correctly-rounded norm.
// ---------------------------------------------------------------------------
__global__ void y2_kernel(const float* __restrict__ y) {
    int i = blockIdx.x * blockDim.x + threadIdx.x;
    if (i < B2) {
        const float4* r = reinterpret_cast<const float4*>(y + (size_t)i * DDIM);
        double s = 0.0;
        #pragma unroll
        for (int t = 0; t < 16; ++t) {
            float4 v = r[t];
            s += (double)v.x * (double)v.x;
            s += (double)v.y * (double)v.y;
            s += (double)v.z * (double)v.z;
            s += (double)v.w * (double)v.w;
        }
        g_y2[i] = (float)s;
    }
}

// ---------------------------------------------------------------------------
// Kernel 2: per (query-block, y-chunk) CTA. Thread owns one query.
// dot computed as STRICT sequential fp32 fmaf chain over k=0..63 (matches
// Eigen gebp / cuBLAS SIMT single-accumulator k-order). Two candidates in
// flight per thread for FFMA-pipe saturation.
// ---------------------------------------------------------------------------
__global__ void __launch_bounds__(QB, 1) knn_partial(
    const float* __restrict__ x, const float* __restrict__ y) {
    __shared__ __align__(16) float ys[TN * DDIM];
    __shared__ float ys2[TN];

    const int qb  = blockIdx.x;
    const int c   = blockIdx.y;
    const int tid = threadIdx.x;
    const int q   = qb * QB + tid;

    // Query row in 64 scalar registers.
    float xr[DDIM];
    {
        const float4* xrow = reinterpret_cast<const float4*>(x + (size_t)q * DDIM);
        #pragma unroll
        for (int t = 0; t < 16; ++t) {
            float4 v = xrow[t];
            xr[4 * t + 0] = v.x; xr[4 * t + 1] = v.y;
            xr[4 * t + 2] = v.z; xr[4 * t + 3] = v.w;
        }
    }
    // x2 in fp64 (per-query constant; uniform shift, rank-irrelevant anyway).
    float x2;
    {
        double s = 0.0;
        #pragma unroll
        for (int k = 0; k < DDIM; ++k) s += (double)xr[k] * (double)xr[k];
        x2 = (float)s;
    }

    float bd[K];           // sorted ascending DISTANCES (sqrt domain)
    int   bi[K];
    #pragma unroll
    for (int u = 0; u < K; ++u) { bd[u] = CUDART_INF_F; bi[u] = 2147483647; }
    float gate2 = CUDART_INF_F;   // safe d^2 bound for "might beat bd[15]"

    const int j0 = c * CHUNK;
    const int j1 = min(j0 + CHUNK, B2);

    for (int t0 = j0; t0 < j1; t0 += TN) {
        __syncthreads();
        // Stage 32 y rows (8 KB) — 512 float4 segments over 256 threads.
        #pragma unroll
        for (int it = 0; it < 2; ++it) {
            int idx = tid + it * QB;
            int r = idx >> 4;
            int s = idx & 15;
            int row = t0 + r;
            float4 v = make_float4(0.f, 0.f, 0.f, 0.f);
            if (row < j1)
                v = reinterpret_cast<const float4*>(y + (size_t)row * DDIM)[s];
            reinterpret_cast<float4*>(ys)[r * 16 + s] = v;
        }
        if (tid < TN) {
            int row = t0 + tid;
            ys2[tid] = (row < j1) ? g_y2[row] : CUDART_INF_F;
        }
        __syncthreads();

        #pragma unroll 1
        for (int jj = 0; jj < TN; jj += 2) {
            const float* y0 = ys + jj * DDIM;
            const float* y1 = y0 + DDIM;
            // Strict sequential fp32 FMA chains (order is load-bearing).
            float a0 = 0.f, a1 = 0.f;
            #pragma unroll
            for (int k = 0; k < DDIM; ++k) {
                a0 = fmaf(xr[k], y0[k], a0);
                a1 = fmaf(xr[k], y1[k], a1);
            }
            float d2_0 = __fsub_rn(__fadd_rn(x2, ys2[jj]),
                                   __fmul_rn(2.f, a0));
            float d2_1 = __fsub_rn(__fadd_rn(x2, ys2[jj + 1]),
                                   __fmul_rn(2.f, a1));

            // Candidate jj (lower index first — stability).
            if (d2_0 < gate2) {
                float dv = __fsqrt_rn(fmaxf(d2_0, 0.f));
                if (dv < bd[K - 1]) {
                    int id = t0 + jj;
                    #pragma unroll
                    for (int u = K - 1; u >= 1; --u) {
                        bool gtc = bd[u]     > dv;
                        bool gtp = bd[u - 1] > dv;
                        float nd = gtp ? bd[u - 1] : dv;
                        int   ni = gtp ? bi[u - 1] : id;
                        if (gtc) { bd[u] = nd; bi[u] = ni; }
                    }
                    if (bd[0] > dv) { bd[0] = dv; bi[0] = id; }
                    float b = bd[K - 1];
                    gate2 = (b == CUDART_INF_F) ? CUDART_INF_F
                                                : b * b * 1.000002f;
                }
            }
            // Candidate jj+1.
            if (d2_1 < gate2) {
                float dv = __fsqrt_rn(fmaxf(d2_1, 0.f));
                if (dv < bd[K - 1]) {
                    int id = t0 + jj + 1;
                    #pragma unroll
                    for (int u = K - 1; u >= 1; --u) {
                        bool gtc = bd[u]     > dv;
                        bool gtp = bd[u - 1] > dv;
                        float nd = gtp ? bd[u - 1] : dv;
                        int   ni = gtp ? bi[u - 1] : id;
                        if (gtc) { bd[u] = nd; bi[u] = ni; }
                    }
                    if (bd[0] > dv) { bd[0] = dv; bi[0] = id; }
                    float b = bd[K - 1];
                    gate2 = (b == CUDART_INF_F) ? CUDART_INF_F
                                                : b * b * 1.000002f;
                }
            }
        }
    }

    const long long base = ((long long)(qb * NCH + c) * QB + tid) * K;
    #pragma unroll
    for (int u = 0; u < K; ++u) {
        g_cand_d[base + u] = bd[u];   // distances (sqrt domain)
        g_cand_i[base + u] = bi[u];
    }
}

// ---------------------------------------------------------------------------
// Kernel 3: merge NCH*16 candidates per query; chunks ascending + strict '<'
// insert => stable index-order ties, matching lax.top_k.
// ---------------------------------------------------------------------------
__global__ void knn_merge(float* __restrict__ out) {
    const int tid = threadIdx.x;
    const int qb  = blockIdx.x;
    const int q   = qb * QB + tid;

    float bd[K];
    int   bi[K];
    #pragma unroll
    for (int u = 0; u < K; ++u) { bd[u] = CUDART_INF_F; bi[u] = 2147483647; }

    for (int cc = 0; cc < NCH; ++cc) {
        const long long base = ((long long)(qb * NCH + cc) * QB + tid) * K;
        #pragma unroll
        for (int u2 = 0; u2 < K; ++u2) {
            float dv = g_cand_d[base + u2];
            int   id = g_cand_i[base + u2];
            if (dv < bd[K - 1]) {
                #pragma unroll
                for (int u = K - 1; u >= 1; --u) {
                    bool gtc = bd[u]     > dv;
                    bool gtp = bd[u - 1] > dv;
                    float nd = gtp ? bd[u - 1] : dv;
                    int   ni = gtp ? bi[u - 1] : id;
                    if (gtc) { bd[u] = nd; bi[u] = ni; }
                }
                if (bd[0] > dv) { bd[0] = dv; bi[0] = id; }
            } else {
                break;  // candidate lists are sorted ascending
            }
        }
    }

    #pragma unroll
    for (int u = 0; u < K; ++u) {
        out[(size_t)q * K + u]                  = bd[u];
        out[(size_t)B1 * K + (size_t)q * K + u] = (float)bi[u];
    }
}

// ---------------------------------------------------------------------------
extern "C" void kernel_launch(void* const* d_in, const int* in_sizes, int n_in,
                              void* d_out, int out_size) {
    const float* x = (const float*)d_in[0];
    const float* y = (const float*)d_in[1];
    float* out = (float*)d_out;

    y2_kernel<<<(B2 + 255) / 256, 256>>>(y);
    dim3 grid(NQB, NCH);
    knn_partial<<<grid, QB>>>(x, y);
    knn_merge<<<NQB, QB>>>(out);
}